// round 11
// baseline (speedup 1.0000x reference)
#include <cuda_runtime.h>
#include <cuda_bf16.h>
#include <math.h>

#define T_DIM 128
#define B_DIM 64
#define C_DIM 768
#define M_DIM (T_DIM * B_DIM)   // 8192
#define K_DW  31
#define EPSF  1e-5f

typedef unsigned long long ull;
typedef unsigned int uint32;

// ---------------- scratch ----------------
__device__ float g_H  [M_DIM * C_DIM];            // layernorm out (fp32, for ffma tiles)
__device__ float g_Y1 [M_DIM * C_DIM];
__device__ float g_S1 [M_DIM * C_DIM];
__device__ float g_D  [M_DIM * C_DIM];
__device__ float g_Y2 [M_DIM * 2 * C_DIM];
__device__ float g_Y3 [M_DIM * C_DIM];
__device__ __nv_bfloat16 g_S2b[M_DIM * C_DIM];
__device__ __nv_bfloat16 g_Sgb[M_DIM * C_DIM];
__device__ __nv_bfloat16 g_Hh[M_DIM * C_DIM];
__device__ __nv_bfloat16 g_Hm[M_DIM * C_DIM];
__device__ __nv_bfloat16 g_Hl[M_DIM * C_DIM];
__device__ __nv_bfloat16 g_W1hi[C_DIM * C_DIM];
__device__ __nv_bfloat16 g_W1mi[C_DIM * C_DIM];
__device__ __nv_bfloat16 g_W1lo[C_DIM * C_DIM];
__device__ __nv_bfloat16 g_W2hi[2 * C_DIM * C_DIM];
__device__ __nv_bfloat16 g_W2mi[2 * C_DIM * C_DIM];
__device__ __nv_bfloat16 g_W2lo[2 * C_DIM * C_DIM];
__device__ __nv_bfloat16 g_Wghi[C_DIM * C_DIM];
__device__ __nv_bfloat16 g_Wgmi[C_DIM * C_DIM];
__device__ __nv_bfloat16 g_Wglo[C_DIM * C_DIM];

// ---------------- packed f32x2 helpers (FFMA2 path) ----------------
__device__ __forceinline__ ull dup2(float v) {
    ull r; asm("mov.b64 %0, {%1, %1};" : "=l"(r) : "f"(v)); return r;
}
__device__ __forceinline__ void fma2(ull &d, ull a, ull b) {
    asm("fma.rn.f32x2 %0, %1, %2, %0;" : "+l"(d) : "l"(a), "l"(b));
}
__device__ __forceinline__ float2 unpack2(ull v) {
    float2 r; asm("mov.b64 {%0, %1}, %2;" : "=f"(r.x), "=f"(r.y) : "l"(v)); return r;
}

// ---------------- mma / ldmatrix / cp.async helpers ----------------
__device__ __forceinline__ void mma_bf16(float* c, const uint32* a, uint32 b0, uint32 b1) {
    asm volatile(
        "mma.sync.aligned.m16n8k16.row.col.f32.bf16.bf16.f32 "
        "{%0,%1,%2,%3}, {%4,%5,%6,%7}, {%8,%9}, {%0,%1,%2,%3};"
        : "+f"(c[0]), "+f"(c[1]), "+f"(c[2]), "+f"(c[3])
        : "r"(a[0]), "r"(a[1]), "r"(a[2]), "r"(a[3]), "r"(b0), "r"(b1));
}
__device__ __forceinline__ void ldsm4(uint32* r, uint32 saddr) {
    asm volatile("ldmatrix.sync.aligned.m8n8.x4.shared.b16 {%0,%1,%2,%3}, [%4];"
        : "=r"(r[0]), "=r"(r[1]), "=r"(r[2]), "=r"(r[3]) : "r"(saddr));
}
#define CP16(dst, src) \
    asm volatile("cp.async.cg.shared.global [%0], [%1], 16;" :: "r"(dst), "l"(src))
#define CP_COMMIT() asm volatile("cp.async.commit_group;" ::: "memory")
#define CP_WAIT1()  asm volatile("cp.async.wait_group 1;" ::: "memory")

// ---------------- weight split ----------------
__global__ void __launch_bounds__(256) split_w_kernel(
    const float* __restrict__ W,
    __nv_bfloat16* __restrict__ hi, __nv_bfloat16* __restrict__ mi,
    __nv_bfloat16* __restrict__ lo, int n)
{
    int i = blockIdx.x * blockDim.x + threadIdx.x;
    if (i >= n) return;
    float w = W[i];
    __nv_bfloat16 h = __float2bfloat16(w);
    float r1 = w - __bfloat162float(h);
    __nv_bfloat16 m = __float2bfloat16(r1);
    float r2 = r1 - __bfloat162float(m);
    hi[i] = h; mi[i] = m; lo[i] = __float2bfloat16(r2);
}

// ---------------- block reduction helper ----------------
__inline__ __device__ float block_reduce_sum(float val, float* shmem) {
    int tid = threadIdx.x;
    #pragma unroll
    for (int o = 16; o > 0; o >>= 1) val += __shfl_xor_sync(0xffffffffu, val, o);
    if ((tid & 31) == 0) shmem[tid >> 5] = val;
    __syncthreads();
    float r = 0.0f;
    if (tid < 8) r = shmem[tid];
    if (tid < 32) {
        #pragma unroll
        for (int o = 4; o > 0; o >>= 1) r += __shfl_xor_sync(0xffffffffu, r, o);
    }
    if (tid == 0) shmem[0] = r;
    __syncthreads();
    r = shmem[0];
    __syncthreads();
    return r;
}

// ---------------- layernorm -> fp32 + 3-way bf16 split output ----------------
__global__ void __launch_bounds__(256) ln_kernel(
    const float* __restrict__ x, const float* __restrict__ gam,
    const float* __restrict__ bet, float* __restrict__ Hf,
    __nv_bfloat16* __restrict__ Hh, __nv_bfloat16* __restrict__ Hm,
    __nv_bfloat16* __restrict__ Hl)
{
    __shared__ float red[32];
    int row = blockIdx.x;
    const float* xr = x + (size_t)row * C_DIM;
    int tid = threadIdx.x;

    float lx[3];
    float s = 0.0f;
    #pragma unroll
    for (int i = 0; i < 3; i++) { lx[i] = xr[tid + i * 256]; s += lx[i]; }
    float mean = block_reduce_sum(s, red) * (1.0f / C_DIM);

    float s2 = 0.0f;
    #pragma unroll
    for (int i = 0; i < 3; i++) { float d = lx[i] - mean; s2 += d * d; }
    float var = block_reduce_sum(s2, red) * (1.0f / C_DIM);
    float rstd = 1.0f / sqrtf(var + EPSF);

    #pragma unroll
    for (int i = 0; i < 3; i++) {
        int c = tid + i * 256;
        float y = (lx[i] - mean) * rstd * gam[c] + bet[c];
        size_t idx = (size_t)row * C_DIM + c;
        Hf[idx] = y;
        __nv_bfloat16 h = __float2bfloat16(y);
        float r1 = y - __bfloat162float(h);
        __nv_bfloat16 m = __float2bfloat16(r1);
        float r2 = r1 - __bfloat162float(m);
        Hh[idx] = h; Hm[idx] = m; Hl[idx] = __float2bfloat16(r2);
    }
}

// ================= GEMM geometry =================
#define GBM 128
#define GBN 64
#define GBK 32
#define ASTR 40                        // halves; 80B row stride

// ---------------- exact fp32 FFMA2 tile (128x64, runs on FMA pipe) -----------
// One full 128x64xK tile computed with fp32 FFMA2 from ORIGINAL fp32 weights.
// A source: fp32 (Afp) or bf16 exact-convert (Abf, for binary spikes).
__device__ __forceinline__ void ffma_tile(
    const __nv_bfloat16* Abf, const float* Afp, const float* Wfp,
    const float* bias, const float* bnp, float* Out,
    int M, int N, int K, char* smraw)
{
    float* As = (float*)smraw;          // [16][132]
    float* Bs = As + 16 * 132;          // [16][68]
    int tid = threadIdx.x;
    int bn0 = blockIdx.x * GBN;
    int bm0 = blockIdx.y * GBM;
    int tx = tid & 15, ty = tid >> 4;
    int lrA = tid & 127, lkA = (tid >> 7) * 8;
    int lrB = tid & 63,  lkB = (tid >> 6) * 4;

    ull acc[8][2];
    #pragma unroll
    for (int i = 0; i < 8; i++) { acc[i][0] = 0ull; acc[i][1] = 0ull; }

    float a8[8];
    float4 pb;
    auto loadA = [&](int k0) {
        if (Afp) {
            float4 v0 = *(const float4*)(Afp + (size_t)(bm0 + lrA) * K + k0 + lkA);
            float4 v1 = *(const float4*)(Afp + (size_t)(bm0 + lrA) * K + k0 + lkA + 4);
            a8[0]=v0.x; a8[1]=v0.y; a8[2]=v0.z; a8[3]=v0.w;
            a8[4]=v1.x; a8[5]=v1.y; a8[6]=v1.z; a8[7]=v1.w;
        } else {
            uint4 v = *(const uint4*)(Abf + (size_t)(bm0 + lrA) * K + k0 + lkA);
            const __nv_bfloat162* hp = (const __nv_bfloat162*)&v;
            #pragma unroll
            for (int j = 0; j < 4; j++) {
                float2 f = __bfloat1622float2(hp[j]);
                a8[2*j] = f.x; a8[2*j+1] = f.y;
            }
        }
    };
    loadA(0);
    pb = *(const float4*)(Wfp + (size_t)(bn0 + lrB) * K + lkB);

    for (int k0 = 0; k0 < K; k0 += 16) {
        __syncthreads();
        #pragma unroll
        for (int i = 0; i < 8; i++) As[(lkA + i) * 132 + lrA] = a8[i];
        Bs[(lkB + 0) * 68 + lrB] = pb.x; Bs[(lkB + 1) * 68 + lrB] = pb.y;
        Bs[(lkB + 2) * 68 + lrB] = pb.z; Bs[(lkB + 3) * 68 + lrB] = pb.w;
        __syncthreads();

        if (k0 + 16 < K) {
            loadA(k0 + 16);
            pb = *(const float4*)(Wfp + (size_t)(bn0 + lrB) * K + k0 + 16 + lkB);
        }

        #pragma unroll
        for (int kk = 0; kk < 16; kk++) {
            float4 av0 = *(const float4*)&As[kk * 132 + ty * 4];
            float4 av1 = *(const float4*)&As[kk * 132 + ty * 4 + 64];
            ulonglong2 bq = *(const ulonglong2*)&Bs[kk * 68 + tx * 4];
            ull bp0 = bq.x, bp1 = bq.y;
            ull a;
            a = dup2(av0.x); fma2(acc[0][0], a, bp0); fma2(acc[0][1], a, bp1);
            a = dup2(av0.y); fma2(acc[1][0], a, bp0); fma2(acc[1][1], a, bp1);
            a = dup2(av0.z); fma2(acc[2][0], a, bp0); fma2(acc[2][1], a, bp1);
            a = dup2(av0.w); fma2(acc[3][0], a, bp0); fma2(acc[3][1], a, bp1);
            a = dup2(av1.x); fma2(acc[4][0], a, bp0); fma2(acc[4][1], a, bp1);
            a = dup2(av1.y); fma2(acc[5][0], a, bp0); fma2(acc[5][1], a, bp1);
            a = dup2(av1.z); fma2(acc[6][0], a, bp0); fma2(acc[6][1], a, bp1);
            a = dup2(av1.w); fma2(acc[7][0], a, bp0); fma2(acc[7][1], a, bp1);
        }
    }

    #pragma unroll
    for (int jp = 0; jp < 2; jp++) {
        int n0 = bn0 + tx * 4 + jp * 2;
        float g0 = bnp[n0],     be0 = bnp[N + n0],     mm0 = bnp[2*N + n0],     vv0 = bnp[3*N + n0];
        float g1 = bnp[n0 + 1], be1 = bnp[N + n0 + 1], mm1 = bnp[2*N + n0 + 1], vv1 = bnp[3*N + n0 + 1];
        float sc0 = g0 / sqrtf(vv0 + EPSF), sh0 = be0 - mm0 * sc0;
        float sc1 = g1 / sqrtf(vv1 + EPSF), sh1 = be1 - mm1 * sc1;
        float bs0 = bias[n0], bs1 = bias[n0 + 1];
        #pragma unroll
        for (int i = 0; i < 8; i++) {
            int m = bm0 + ty * 4 + ((i < 4) ? i : (64 + i - 4));
            float2 v = unpack2(acc[i][jp]);
            float2 o;
            o.x = (v.x + bs0) * sc0 + sh0;
            o.y = (v.y + bs1) * sc1 + sh1;
            *(float2*)&Out[(size_t)m * N + n0] = o;
        }
    }
}

// ---------------- spike GEMM (binary A, 3 W splits) + ffma tiles --------------
#define AH   (GBM * ASTR)
#define BH   (GBN * ASTR)
#define STG  (AH + 3 * BH)
#define SPIKE_SMEM (2 * STG * 2)

__global__ void __launch_bounds__(256) gemm_spike_bf16(
    const __nv_bfloat16* __restrict__ A,
    const __nv_bfloat16* __restrict__ Whi, const __nv_bfloat16* __restrict__ Wmi,
    const __nv_bfloat16* __restrict__ Wlo,
    const float* __restrict__ Wfp, int NFF,
    const float* __restrict__ bias, const float* __restrict__ bnp,
    float* __restrict__ Out, int M, int N, int K)
{
    extern __shared__ __align__(1024) char smraw[];
    if ((int)blockIdx.x < NFF) {
        ffma_tile(A, nullptr, Wfp, bias, bnp, Out, M, N, K, smraw);
        return;
    }
    unsigned short* sm = (unsigned short*)smraw;
    uint32 smb = (uint32)__cvta_generic_to_shared(sm);

    int tid = threadIdx.x;
    int wid = tid >> 5, lane = tid & 31;
    int wm = wid & 3, wn = wid >> 2;
    int bn0 = blockIdx.x * GBN, bm0 = blockIdx.y * GBM;

    int ldrow = tid >> 2;
    int ldcol = (tid & 3) * 8;

    float acc[2][4][4];
    #pragma unroll
    for (int mt = 0; mt < 2; mt++)
        #pragma unroll
        for (int nt = 0; nt < 4; nt++)
            #pragma unroll
            for (int q = 0; q < 4; q++) acc[mt][nt][q] = 0.0f;

    int a_row = (lane & 7) + ((lane >> 3) & 1) * 8;
    int a_ko  = ((lane >> 4) & 1) * 8;
    int b_row = (lane & 7) + ((lane >> 4) & 1) * 8;
    int b_ko  = ((lane >> 3) & 1) * 8;

    auto issue = [&](int st, int k0) {
        #pragma unroll
        for (int j = 0; j < 2; j++) {
            int row = ldrow + j * 64;
            uint32 dst = smb + (uint32)(st * STG + row * ASTR + ldcol) * 2;
            CP16(dst, A + (size_t)(bm0 + row) * K + k0 + ldcol);
        }
        uint32 dst = smb + (uint32)(st * STG + AH + ldrow * ASTR + ldcol) * 2;
        CP16(dst, Whi + (size_t)(bn0 + ldrow) * K + k0 + ldcol);
        dst += (uint32)BH * 2;
        CP16(dst, Wmi + (size_t)(bn0 + ldrow) * K + k0 + ldcol);
        dst += (uint32)BH * 2;
        CP16(dst, Wlo + (size_t)(bn0 + ldrow) * K + k0 + ldcol);
    };

    int NCH = K / GBK;
    issue(0, 0);
    CP_COMMIT();

    for (int ch = 0; ch < NCH; ch++) {
        if (ch + 1 < NCH) issue((ch + 1) & 1, (ch + 1) * GBK);
        CP_COMMIT();
        CP_WAIT1();
        __syncthreads();

        int st = ch & 1;
        uint32 abase = smb + (uint32)(st * STG) * 2;
        uint32 bbase = smb + (uint32)(st * STG + AH) * 2;

        #pragma unroll
        for (int ks = 0; ks < 2; ks++) {
            int kc = ks * 16;
            uint32 af[2][4];
            #pragma unroll
            for (int mt = 0; mt < 2; mt++)
                ldsm4(af[mt], abase + (uint32)((wm * 32 + mt * 16 + a_row) * ASTR + kc + a_ko) * 2);
            #pragma unroll
            for (int s = 0; s < 3; s++) {
                #pragma unroll
                for (int g = 0; g < 2; g++) {
                    uint32 bf[4];
                    ldsm4(bf, bbase + (uint32)(s * BH + (wn * 32 + g * 16 + b_row) * ASTR + kc + b_ko) * 2);
                    mma_bf16(acc[0][2 * g],     af[0], bf[0], bf[1]);
                    mma_bf16(acc[1][2 * g],     af[1], bf[0], bf[1]);
                    mma_bf16(acc[0][2 * g + 1], af[0], bf[2], bf[3]);
                    mma_bf16(acc[1][2 * g + 1], af[1], bf[2], bf[3]);
                }
            }
        }
        __syncthreads();
    }

    int r4 = lane >> 2, c2 = (lane & 3) * 2;
    #pragma unroll
    for (int nt = 0; nt < 4; nt++) {
        int n0 = bn0 + wn * 32 + nt * 8 + c2;
        float g0 = bnp[n0],     be0 = bnp[N + n0],     mm0 = bnp[2*N + n0],     vv0 = bnp[3*N + n0];
        float g1 = bnp[n0 + 1], be1 = bnp[N + n0 + 1], mm1 = bnp[2*N + n0 + 1], vv1 = bnp[3*N + n0 + 1];
        float sc0 = g0 / sqrtf(vv0 + EPSF), sh0 = be0 - mm0 * sc0;
        float sc1 = g1 / sqrtf(vv1 + EPSF), sh1 = be1 - mm1 * sc1;
        float bs0 = bias[n0], bs1 = bias[n0 + 1];
        #pragma unroll
        for (int mt = 0; mt < 2; mt++) {
            int m0 = bm0 + wm * 32 + mt * 16 + r4;
            float2 o0, o1;
            o0.x = (acc[mt][nt][0] + bs0) * sc0 + sh0;
            o0.y = (acc[mt][nt][1] + bs1) * sc1 + sh1;
            o1.x = (acc[mt][nt][2] + bs0) * sc0 + sh0;
            o1.y = (acc[mt][nt][3] + bs1) * sc1 + sh1;
            *(float2*)&Out[(size_t)m0 * N + n0] = o0;
            *(float2*)&Out[(size_t)(m0 + 8) * N + n0] = o1;
        }
    }
}

// ---------------- 6-term split GEMM + ffma tiles ------------------------------
#define S6_AH (GBM * ASTR)
#define S6_BH (GBN * ASTR)
#define S6_STG (3 * S6_AH + 3 * S6_BH)
#define S6_SMEM (2 * S6_STG * 2)

__global__ void __launch_bounds__(256) gemm_split6_bf16(
    const __nv_bfloat16* __restrict__ Ah, const __nv_bfloat16* __restrict__ Am,
    const __nv_bfloat16* __restrict__ Al,
    const __nv_bfloat16* __restrict__ Wh, const __nv_bfloat16* __restrict__ Wm,
    const __nv_bfloat16* __restrict__ Wl,
    const float* __restrict__ Afp, const float* __restrict__ Wfp, int NFF,
    const float* __restrict__ bias, const float* __restrict__ bnp,
    float* __restrict__ Out, int M, int N, int K)
{
    extern __shared__ __align__(1024) char smraw[];
    if ((int)blockIdx.x < NFF) {
        ffma_tile(nullptr, Afp, Wfp, bias, bnp, Out, M, N, K, smraw);
        return;
    }
    unsigned short* sm = (unsigned short*)smraw;
    uint32 smb = (uint32)__cvta_generic_to_shared(sm);

    int tid = threadIdx.x;
    int wid = tid >> 5, lane = tid & 31;
    int wm = wid & 3, wn = wid >> 2;
    int bn0 = blockIdx.x * GBN, bm0 = blockIdx.y * GBM;

    int ldrow = tid >> 2;
    int ldcol = (tid & 3) * 8;

    const __nv_bfloat16* Asel[3] = {Ah, Am, Al};
    const __nv_bfloat16* Wsel[3] = {Wh, Wm, Wl};

    float acc[2][4][4];
    #pragma unroll
    for (int mt = 0; mt < 2; mt++)
        #pragma unroll
        for (int nt = 0; nt < 4; nt++)
            #pragma unroll
            for (int q = 0; q < 4; q++) acc[mt][nt][q] = 0.0f;

    int a_row = (lane & 7) + ((lane >> 3) & 1) * 8;
    int a_ko  = ((lane >> 4) & 1) * 8;
    int b_row = (lane & 7) + ((lane >> 4) & 1) * 8;
    int b_ko  = ((lane >> 3) & 1) * 8;

    auto issue = [&](int st, int k0) {
        #pragma unroll
        for (int s = 0; s < 3; s++) {
            #pragma unroll
            for (int j = 0; j < 2; j++) {
                int row = ldrow + j * 64;
                uint32 dst = smb + (uint32)(st * S6_STG + s * S6_AH + row * ASTR + ldcol) * 2;
                CP16(dst, Asel[s] + (size_t)(bm0 + row) * K + k0 + ldcol);
            }
            uint32 dst = smb + (uint32)(st * S6_STG + 3 * S6_AH + s * S6_BH + ldrow * ASTR + ldcol) * 2;
            CP16(dst, Wsel[s] + (size_t)(bn0 + ldrow) * K + k0 + ldcol);
        }
    };

    int NCH = K / GBK;
    issue(0, 0);
    CP_COMMIT();

    for (int ch = 0; ch < NCH; ch++) {
        if (ch + 1 < NCH) issue((ch + 1) & 1, (ch + 1) * GBK);
        CP_COMMIT();
        CP_WAIT1();
        __syncthreads();

        int st = ch & 1;
        uint32 abase = smb + (uint32)(st * S6_STG) * 2;
        uint32 bbase = smb + (uint32)(st * S6_STG + 3 * S6_AH) * 2;

        #pragma unroll
        for (int ks = 0; ks < 2; ks++) {
            int kc = ks * 16;
            uint32 af[3][2][4];
            #pragma unroll
            for (int s = 0; s < 3; s++)
                #pragma unroll
                for (int mt = 0; mt < 2; mt++)
                    ldsm4(af[s][mt], abase + (uint32)(s * S6_AH + (wm * 32 + mt * 16 + a_row) * ASTR + kc + a_ko) * 2);
            #pragma unroll
            for (int t = 0; t < 3; t++) {
                #pragma unroll
                for (int g = 0; g < 2; g++) {
                    uint32 bf[4];
                    ldsm4(bf, bbase + (uint32)(t * S6_BH + (wn * 32 + g * 16 + b_row) * ASTR + kc + b_ko) * 2);
                    #pragma unroll
                    for (int s = 0; s < 3; s++) {
                        if (s + t <= 2) {
                            mma_bf16(acc[0][2 * g],     af[s][0], bf[0], bf[1]);
                            mma_bf16(acc[1][2 * g],     af[s][1], bf[0], bf[1]);
                            mma_bf16(acc[0][2 * g + 1], af[s][0], bf[2], bf[3]);
                            mma_bf16(acc[1][2 * g + 1], af[s][1], bf[2], bf[3]);
                        }
                    }
                }
            }
        }
        __syncthreads();
    }

    int r4 = lane >> 2, c2 = (lane & 3) * 2;
    #pragma unroll
    for (int nt = 0; nt < 4; nt++) {
        int n0 = bn0 + wn * 32 + nt * 8 + c2;
        float g0 = bnp[n0],     be0 = bnp[N + n0],     mm0 = bnp[2*N + n0],     vv0 = bnp[3*N + n0];
        float g1 = bnp[n0 + 1], be1 = bnp[N + n0 + 1], mm1 = bnp[2*N + n0 + 1], vv1 = bnp[3*N + n0 + 1];
        float sc0 = g0 / sqrtf(vv0 + EPSF), sh0 = be0 - mm0 * sc0;
        float sc1 = g1 / sqrtf(vv1 + EPSF), sh1 = be1 - mm1 * sc1;
        float bs0 = bias[n0], bs1 = bias[n0 + 1];
        #pragma unroll
        for (int mt = 0; mt < 2; mt++) {
            int m0 = bm0 + wm * 32 + mt * 16 + r4;
            float2 o0, o1;
            o0.x = (acc[mt][nt][0] + bs0) * sc0 + sh0;
            o0.y = (acc[mt][nt][1] + bs1) * sc1 + sh1;
            o1.x = (acc[mt][nt][2] + bs0) * sc0 + sh0;
            o1.y = (acc[mt][nt][3] + bs1) * sc1 + sh1;
            *(float2*)&Out[(size_t)m0 * N + n0] = o0;
            *(float2*)&Out[(size_t)(m0 + 8) * N + n0] = o1;
        }
    }
}

// ---------------- LIF scan ----------------
template<typename OutT>
__global__ void __launch_bounds__(256) lif_kernel(
    const float* __restrict__ X, int ldx,
    const float* __restrict__ bnp,
    OutT* __restrict__ S)
{
    int j = blockIdx.x * blockDim.x + threadIdx.x;
    if (j >= B_DIM * C_DIM) return;
    int b = j / C_DIM, c = j % C_DIM;

    float sc = 1.0f, sh = 0.0f;
    if (bnp) {
        float g = bnp[c], be = bnp[C_DIM + c], mm = bnp[2 * C_DIM + c], vv = bnp[3 * C_DIM + c];
        sc = g / sqrtf(vv + EPSF);
        sh = be - mm * sc;
    }

    const float* xp = X + (size_t)b * ldx + c;
    OutT* sp = S + (size_t)j;
    size_t stx = (size_t)B_DIM * ldx;
    size_t sts = (size_t)B_DIM * C_DIM;

    float vm = 0.0f;
    #pragma unroll 4
    for (int t = 0; t < T_DIM; t++) {
        float xv = xp[(size_t)t * stx] * sc + sh;
        vm = vm * 0.5f + xv;
        float s = (vm >= 1.0f) ? 1.0f : 0.0f;
        vm = (s > 0.0f) ? 0.0f : vm;
        sp[(size_t)t * sts] = (OutT)s;
    }
}

// ---------------- fused final double-LIF: s9=lif(Y3); out=lif(Y2out*s9) ------
__global__ void __launch_bounds__(256) lif_final_kernel(
    const float* __restrict__ Y3, const float* __restrict__ Y2out,
    float* __restrict__ Out)
{
    int j = blockIdx.x * blockDim.x + threadIdx.x;
    if (j >= B_DIM * C_DIM) return;
    int b = j / C_DIM, c = j % C_DIM;
    const float* yp = Y3 + (size_t)b * C_DIM + c;
    const float* op = Y2out + (size_t)b * 2 * C_DIM + c;
    float* sp = Out + (size_t)j;
    size_t st3 = (size_t)B_DIM * C_DIM;
    size_t st2 = (size_t)B_DIM * 2 * C_DIM;

    float v9 = 0.0f, v10 = 0.0f;
    #pragma unroll 4
    for (int t = 0; t < T_DIM; t++) {
        float g = yp[(size_t)t * st3];
        v9 = v9 * 0.5f + g;
        float s9 = (v9 >= 1.0f) ? 1.0f : 0.0f;
        v9 = (s9 > 0.0f) ? 0.0f : v9;
        float x = op[(size_t)t * st2] * s9;
        v10 = v10 * 0.5f + x;
        float s10 = (v10 >= 1.0f) ? 1.0f : 0.0f;
        v10 = (s10 > 0.0f) ? 0.0f : v10;
        sp[(size_t)t * st3] = s10;
    }
}

// ---------------- depthwise conv over time ----------------
#define DW_PAD 15
__global__ void __launch_bounds__(256) dw_kernel(
    const float* __restrict__ S1, const float* __restrict__ w,
    const float* __restrict__ bvec, float* __restrict__ Dout)
{
    __shared__ float sx[T_DIM + 2 * DW_PAD][64];
    int b  = blockIdx.x;
    int c0 = blockIdx.y * 64;
    int tid = threadIdx.x;

    for (int i = tid; i < 2 * DW_PAD * 64; i += 256) {
        int r = i >> 6, ci = i & 63;
        if (r < DW_PAD) sx[r][ci] = 0.0f;
        else            sx[T_DIM + DW_PAD + (r - DW_PAD)][ci] = 0.0f;
    }
    for (int i = tid; i < T_DIM * 64; i += 256) {
        int t = i >> 6, ci = i & 63;
        sx[t + DW_PAD][ci] = S1[((size_t)t * B_DIM + b) * C_DIM + c0 + ci];
    }
    __syncthreads();

    int ci = tid & 63;
    int tg = tid >> 6;
    int c  = c0 + ci;
    int t0 = tg * 32;

    float wr[K_DW];
    #pragma unroll
    for (int k = 0; k < K_DW; k++) wr[k] = w[c * K_DW + k];
    float bb = bvec[c];

    float acc[32];
    #pragma unroll
    for (int i = 0; i < 32; i++) acc[i] = bb;

    #pragma unroll
    for (int dt = -DW_PAD; dt <= 31 + DW_PAD; dt++) {
        float sv = sx[t0 + dt + DW_PAD][ci];
        #pragma unroll
        for (int i = 0; i < 32; i++) {
            int k = dt - i + DW_PAD;
            if (k >= 0 && k < K_DW) acc[i] += sv * wr[k];
        }
    }

    #pragma unroll
    for (int i = 0; i < 32; i++) {
        int t = t0 + i;
        Dout[((size_t)t * B_DIM + b) * C_DIM + c] = acc[i];
    }
}

// ---------------- launch ----------------
extern "C" void kernel_launch(void* const* d_in, const int* in_sizes, int n_in,
                              void* d_out, int out_size)
{
    const float* x        = (const float*)d_in[0];
    const float* ln_g     = (const float*)d_in[1];
    const float* ln_b     = (const float*)d_in[2];
    const float* pw1_w    = (const float*)d_in[3];
    const float* pw1_b    = (const float*)d_in[4];
    const float* bn1_p    = (const float*)d_in[5];
    const float* dw_w     = (const float*)d_in[6];
    const float* dw_b     = (const float*)d_in[7];
    const float* bn2_p    = (const float*)d_in[8];
    const float* pw2_w    = (const float*)d_in[9];
    const float* pw2_b    = (const float*)d_in[10];
    const float* bn3_p    = (const float*)d_in[11];
    const float* gsu_w    = (const float*)d_in[12];
    const float* gsu_b    = (const float*)d_in[13];
    const float* gsu_bn_p = (const float*)d_in[14];

    float *H, *Y1, *S1, *D, *Y2, *Y3;
    __nv_bfloat16 *S2b, *Sgb, *Hh, *Hm, *Hl;
    __nv_bfloat16 *W1hi, *W1mi, *W1lo, *W2hi, *W2mi, *W2lo, *Wghi, *Wgmi, *Wglo;
    cudaGetSymbolAddress((void**)&H,    g_H);
    cudaGetSymbolAddress((void**)&Y1,   g_Y1);
    cudaGetSymbolAddress((void**)&S1,   g_S1);
    cudaGetSymbolAddress((void**)&D,    g_D);
    cudaGetSymbolAddress((void**)&Y2,   g_Y2);
    cudaGetSymbolAddress((void**)&Y3,   g_Y3);
    cudaGetSymbolAddress((void**)&S2b,  g_S2b);
    cudaGetSymbolAddress((void**)&Sgb,  g_Sgb);
    cudaGetSymbolAddress((void**)&Hh,   g_Hh);
    cudaGetSymbolAddress((void**)&Hm,   g_Hm);
    cudaGetSymbolAddress((void**)&Hl,   g_Hl);
    cudaGetSymbolAddress((void**)&W1hi, g_W1hi);
    cudaGetSymbolAddress((void**)&W1mi, g_W1mi);
    cudaGetSymbolAddress((void**)&W1lo, g_W1lo);
    cudaGetSymbolAddress((void**)&W2hi, g_W2hi);
    cudaGetSymbolAddress((void**)&W2mi, g_W2mi);
    cudaGetSymbolAddress((void**)&W2lo, g_W2lo);
    cudaGetSymbolAddress((void**)&Wghi, g_Wghi);
    cudaGetSymbolAddress((void**)&Wgmi, g_Wgmi);
    cudaGetSymbolAddress((void**)&Wglo, g_Wglo);

    // idempotent, every invocation
    cudaFuncSetAttribute(gemm_spike_bf16,
        cudaFuncAttributeMaxDynamicSharedMemorySize, SPIKE_SMEM);
    cudaFuncSetAttribute(gemm_split6_bf16,
        cudaFuncAttributeMaxDynamicSharedMemorySize, S6_SMEM);

    const int lif_blocks = (B_DIM * C_DIM + 255) / 256;   // 192

    // 0) weight splits
    split_w_kernel<<<(C_DIM * C_DIM + 255) / 256, 256>>>(pw1_w, W1hi, W1mi, W1lo, C_DIM * C_DIM);
    split_w_kernel<<<(2 * C_DIM * C_DIM + 255) / 256, 256>>>(pw2_w, W2hi, W2mi, W2lo, 2 * C_DIM * C_DIM);
    split_w_kernel<<<(C_DIM * C_DIM + 255) / 256, 256>>>(gsu_w, Wghi, Wgmi, Wglo, C_DIM * C_DIM);

    // 1) LayerNorm -> fp32 H + bf16 splits
    ln_kernel<<<M_DIM, 256>>>(x, ln_g, ln_b, H, Hh, Hm, Hl);

    // 2) pw1 + bias + bn1 (hybrid: 1 ffma tile-col + 11 mma tile-cols)
    gemm_split6_bf16<<<dim3(C_DIM / GBN, M_DIM / GBM), 256, S6_SMEM>>>(
        Hh, Hm, Hl, W1hi, W1mi, W1lo, H, pw1_w, 1, pw1_b, bn1_p, Y1, M_DIM, C_DIM, C_DIM);

    // 3) LIF -> S1
    lif_kernel<float><<<lif_blocks, 256>>>(Y1, C_DIM, nullptr, S1);

    // 4) depthwise
    dw_kernel<<<dim3(B_DIM, C_DIM / 64), 256>>>(S1, dw_w, dw_b, D);

    // 5) BN2 + LIF -> S2 (bf16)
    lif_kernel<__nv_bfloat16><<<lif_blocks, 256>>>(D, C_DIM, bn2_p, S2b);

    // 6) pw2 + bias + bn3 (hybrid: 2 ffma + 22 mma tile-cols)
    gemm_spike_bf16<<<dim3(2 * C_DIM / GBN, M_DIM / GBM), 256, SPIKE_SMEM>>>(
        S2b, W2hi, W2mi, W2lo, pw2_w, 2, pw2_b, bn3_p, Y2, M_DIM, 2 * C_DIM, C_DIM);

    // 7) LIF(gate) -> Sg (bf16)
    lif_kernel<__nv_bfloat16><<<lif_blocks, 256>>>(Y2 + C_DIM, 2 * C_DIM, nullptr, Sgb);

    // 8) gsu GEMM (hybrid: 1 ffma + 11 mma tile-cols)
    gemm_spike_bf16<<<dim3(C_DIM / GBN, M_DIM / GBM), 256, SPIKE_SMEM>>>(
        Sgb, Wghi, Wgmi, Wglo, gsu_w, 1, gsu_b, gsu_bn_p, Y3, M_DIM, C_DIM, C_DIM);

    // 9+10) fused: s9 = lif(Y3); out = lif(Y2out * s9)
    lif_final_kernel<<<lif_blocks, 256>>>(Y3, Y2, (float*)d_out);
}

// round 12
// speedup vs baseline: 1.2179x; 1.2179x over previous
#include <cuda_runtime.h>
#include <cuda_bf16.h>
#include <math.h>

#define T_DIM 128
#define B_DIM 64
#define C_DIM 768
#define M_DIM (T_DIM * B_DIM)   // 8192
#define K_DW  31
#define EPSF  1e-5f

typedef unsigned long long ull;
typedef unsigned int uint32;
typedef unsigned short ushort;

// ---------------- scratch ----------------
__device__ float g_Y1 [M_DIM * C_DIM];
__device__ float g_Y2 [M_DIM * 2 * C_DIM];
__device__ float g_Y3 [M_DIM * C_DIM];
__device__ __nv_bfloat16 g_S2b[M_DIM * C_DIM];
__device__ __nv_bfloat16 g_Sgb[M_DIM * C_DIM];
__device__ __nv_bfloat16 g_Hh[M_DIM * C_DIM];
__device__ __nv_bfloat16 g_Hm[M_DIM * C_DIM];
__device__ __nv_bfloat16 g_Hl[M_DIM * C_DIM];
__device__ __nv_bfloat16 g_W1hi[C_DIM * C_DIM];
__device__ __nv_bfloat16 g_W1mi[C_DIM * C_DIM];
__device__ __nv_bfloat16 g_W1lo[C_DIM * C_DIM];
__device__ __nv_bfloat16 g_W2hi[2 * C_DIM * C_DIM];
__device__ __nv_bfloat16 g_W2mi[2 * C_DIM * C_DIM];
__device__ __nv_bfloat16 g_W2lo[2 * C_DIM * C_DIM];
__device__ __nv_bfloat16 g_Wghi[C_DIM * C_DIM];
__device__ __nv_bfloat16 g_Wgmi[C_DIM * C_DIM];
__device__ __nv_bfloat16 g_Wglo[C_DIM * C_DIM];

// ---------------- mma / ldmatrix / cp.async helpers ----------------
__device__ __forceinline__ void mma_bf16(float* c, const uint32* a, uint32 b0, uint32 b1) {
    asm volatile(
        "mma.sync.aligned.m16n8k16.row.col.f32.bf16.bf16.f32 "
        "{%0,%1,%2,%3}, {%4,%5,%6,%7}, {%8,%9}, {%0,%1,%2,%3};"
        : "+f"(c[0]), "+f"(c[1]), "+f"(c[2]), "+f"(c[3])
        : "r"(a[0]), "r"(a[1]), "r"(a[2]), "r"(a[3]), "r"(b0), "r"(b1));
}
__device__ __forceinline__ void ldsm4(uint32* r, uint32 saddr) {
    asm volatile("ldmatrix.sync.aligned.m8n8.x4.shared.b16 {%0,%1,%2,%3}, [%4];"
        : "=r"(r[0]), "=r"(r[1]), "=r"(r[2]), "=r"(r[3]) : "r"(saddr));
}
#define CP16(dst, src) \
    asm volatile("cp.async.cg.shared.global [%0], [%1], 16;" :: "r"(dst), "l"(src))
#define CP_COMMIT() asm volatile("cp.async.commit_group;" ::: "memory")
#define CP_WAIT1()  asm volatile("cp.async.wait_group 1;" ::: "memory")

// ---------------- weight split ----------------
__global__ void __launch_bounds__(256) split_w_kernel(
    const float* __restrict__ W,
    __nv_bfloat16* __restrict__ hi, __nv_bfloat16* __restrict__ mi,
    __nv_bfloat16* __restrict__ lo, int n)
{
    int i = blockIdx.x * blockDim.x + threadIdx.x;
    if (i >= n) return;
    float w = W[i];
    __nv_bfloat16 h = __float2bfloat16(w);
    float r1 = w - __bfloat162float(h);
    __nv_bfloat16 m = __float2bfloat16(r1);
    float r2 = r1 - __bfloat162float(m);
    hi[i] = h; mi[i] = m; lo[i] = __float2bfloat16(r2);
}

// ---------------- block reduction helper ----------------
__inline__ __device__ float block_reduce_sum(float val, float* shmem) {
    int tid = threadIdx.x;
    #pragma unroll
    for (int o = 16; o > 0; o >>= 1) val += __shfl_xor_sync(0xffffffffu, val, o);
    if ((tid & 31) == 0) shmem[tid >> 5] = val;
    __syncthreads();
    float r = 0.0f;
    if (tid < 8) r = shmem[tid];
    if (tid < 32) {
        #pragma unroll
        for (int o = 4; o > 0; o >>= 1) r += __shfl_xor_sync(0xffffffffu, r, o);
    }
    if (tid == 0) shmem[0] = r;
    __syncthreads();
    r = shmem[0];
    __syncthreads();
    return r;
}

// ---------------- layernorm -> 3-way bf16 split output ----------------
__global__ void __launch_bounds__(256) ln_kernel(
    const float* __restrict__ x, const float* __restrict__ gam,
    const float* __restrict__ bet,
    __nv_bfloat16* __restrict__ Hh, __nv_bfloat16* __restrict__ Hm,
    __nv_bfloat16* __restrict__ Hl)
{
    __shared__ float red[32];
    int row = blockIdx.x;
    const float* xr = x + (size_t)row * C_DIM;
    int tid = threadIdx.x;

    float lx[3];
    float s = 0.0f;
    #pragma unroll
    for (int i = 0; i < 3; i++) { lx[i] = xr[tid + i * 256]; s += lx[i]; }
    float mean = block_reduce_sum(s, red) * (1.0f / C_DIM);

    float s2 = 0.0f;
    #pragma unroll
    for (int i = 0; i < 3; i++) { float d = lx[i] - mean; s2 += d * d; }
    float var = block_reduce_sum(s2, red) * (1.0f / C_DIM);
    float rstd = 1.0f / sqrtf(var + EPSF);

    #pragma unroll
    for (int i = 0; i < 3; i++) {
        int c = tid + i * 256;
        float y = (lx[i] - mean) * rstd * gam[c] + bet[c];
        __nv_bfloat16 h = __float2bfloat16(y);
        float r1 = y - __bfloat162float(h);
        __nv_bfloat16 m = __float2bfloat16(r1);
        float r2 = r1 - __bfloat162float(m);
        size_t idx = (size_t)row * C_DIM + c;
        Hh[idx] = h; Hm[idx] = m; Hl[idx] = __float2bfloat16(r2);
    }
}

// ================= GEMM geometry =================
#define GBM 128
#define GBN 64
#define GBK 32
#define ASTR 40                        // halves; 80B row stride

// ---------------- spike GEMM (binary A, 3 W splits) ----------------
#define AH   (GBM * ASTR)
#define BH   (GBN * ASTR)
#define STG  (AH + 3 * BH)
#define SPIKE_SMEM (2 * STG * 2)

__global__ void __launch_bounds__(256) gemm_spike_bf16(
    const __nv_bfloat16* __restrict__ A,
    const __nv_bfloat16* __restrict__ Whi, const __nv_bfloat16* __restrict__ Wmi,
    const __nv_bfloat16* __restrict__ Wlo,
    const float* __restrict__ bias, const float* __restrict__ bnp,
    float* __restrict__ Out, int M, int N, int K)
{
    extern __shared__ __align__(16) unsigned short sm[];
    uint32 smb = (uint32)__cvta_generic_to_shared(sm);

    int tid = threadIdx.x;
    int wid = tid >> 5, lane = tid & 31;
    int wm = wid & 3, wn = wid >> 2;
    int bn0 = blockIdx.x * GBN, bm0 = blockIdx.y * GBM;

    int ldrow = tid >> 2;
    int ldcol = (tid & 3) * 8;

    float acc[2][4][4];
    #pragma unroll
    for (int mt = 0; mt < 2; mt++)
        #pragma unroll
        for (int nt = 0; nt < 4; nt++)
            #pragma unroll
            for (int q = 0; q < 4; q++) acc[mt][nt][q] = 0.0f;

    int a_row = (lane & 7) + ((lane >> 3) & 1) * 8;
    int a_ko  = ((lane >> 4) & 1) * 8;
    int b_row = (lane & 7) + ((lane >> 4) & 1) * 8;
    int b_ko  = ((lane >> 3) & 1) * 8;

    auto issue = [&](int st, int k0) {
        #pragma unroll
        for (int j = 0; j < 2; j++) {
            int row = ldrow + j * 64;
            uint32 dst = smb + (uint32)(st * STG + row * ASTR + ldcol) * 2;
            CP16(dst, A + (size_t)(bm0 + row) * K + k0 + ldcol);
        }
        uint32 dst = smb + (uint32)(st * STG + AH + ldrow * ASTR + ldcol) * 2;
        CP16(dst, Whi + (size_t)(bn0 + ldrow) * K + k0 + ldcol);
        dst += (uint32)BH * 2;
        CP16(dst, Wmi + (size_t)(bn0 + ldrow) * K + k0 + ldcol);
        dst += (uint32)BH * 2;
        CP16(dst, Wlo + (size_t)(bn0 + ldrow) * K + k0 + ldcol);
    };

    int NCH = K / GBK;
    issue(0, 0);
    CP_COMMIT();

    for (int ch = 0; ch < NCH; ch++) {
        if (ch + 1 < NCH) issue((ch + 1) & 1, (ch + 1) * GBK);
        CP_COMMIT();
        CP_WAIT1();
        __syncthreads();

        int st = ch & 1;
        uint32 abase = smb + (uint32)(st * STG) * 2;
        uint32 bbase = smb + (uint32)(st * STG + AH) * 2;

        #pragma unroll
        for (int ks = 0; ks < 2; ks++) {
            int kc = ks * 16;
            uint32 af[2][4];
            #pragma unroll
            for (int mt = 0; mt < 2; mt++)
                ldsm4(af[mt], abase + (uint32)((wm * 32 + mt * 16 + a_row) * ASTR + kc + a_ko) * 2);
            #pragma unroll
            for (int s = 0; s < 3; s++) {
                #pragma unroll
                for (int g = 0; g < 2; g++) {
                    uint32 bf[4];
                    ldsm4(bf, bbase + (uint32)(s * BH + (wn * 32 + g * 16 + b_row) * ASTR + kc + b_ko) * 2);
                    mma_bf16(acc[0][2 * g],     af[0], bf[0], bf[1]);
                    mma_bf16(acc[1][2 * g],     af[1], bf[0], bf[1]);
                    mma_bf16(acc[0][2 * g + 1], af[0], bf[2], bf[3]);
                    mma_bf16(acc[1][2 * g + 1], af[1], bf[2], bf[3]);
                }
            }
        }
        __syncthreads();
    }

    int r4 = lane >> 2, c2 = (lane & 3) * 2;
    #pragma unroll
    for (int nt = 0; nt < 4; nt++) {
        int n0 = bn0 + wn * 32 + nt * 8 + c2;
        float g0 = bnp[n0],     be0 = bnp[N + n0],     mm0 = bnp[2*N + n0],     vv0 = bnp[3*N + n0];
        float g1 = bnp[n0 + 1], be1 = bnp[N + n0 + 1], mm1 = bnp[2*N + n0 + 1], vv1 = bnp[3*N + n0 + 1];
        float sc0 = g0 / sqrtf(vv0 + EPSF), sh0 = be0 - mm0 * sc0;
        float sc1 = g1 / sqrtf(vv1 + EPSF), sh1 = be1 - mm1 * sc1;
        float bs0 = bias[n0], bs1 = bias[n0 + 1];
        #pragma unroll
        for (int mt = 0; mt < 2; mt++) {
            int m0 = bm0 + wm * 32 + mt * 16 + r4;
            float2 o0, o1;
            o0.x = (acc[mt][nt][0] + bs0) * sc0 + sh0;
            o0.y = (acc[mt][nt][1] + bs1) * sc1 + sh1;
            o1.x = (acc[mt][nt][2] + bs0) * sc0 + sh0;
            o1.y = (acc[mt][nt][3] + bs1) * sc1 + sh1;
            *(float2*)&Out[(size_t)m0 * N + n0] = o0;
            *(float2*)&Out[(size_t)(m0 + 8) * N + n0] = o1;
        }
    }
}

// ---------------- 6-term split GEMM (fp32-accurate, A & W both split) ---------
#define S6_AH (GBM * ASTR)
#define S6_BH (GBN * ASTR)
#define S6_STG (3 * S6_AH + 3 * S6_BH)
#define S6_SMEM (2 * S6_STG * 2)

__global__ void __launch_bounds__(256) gemm_split6_bf16(
    const __nv_bfloat16* __restrict__ Ah, const __nv_bfloat16* __restrict__ Am,
    const __nv_bfloat16* __restrict__ Al,
    const __nv_bfloat16* __restrict__ Wh, const __nv_bfloat16* __restrict__ Wm,
    const __nv_bfloat16* __restrict__ Wl,
    const float* __restrict__ bias, const float* __restrict__ bnp,
    float* __restrict__ Out, int M, int N, int K)
{
    extern __shared__ __align__(16) unsigned short sm[];
    uint32 smb = (uint32)__cvta_generic_to_shared(sm);

    int tid = threadIdx.x;
    int wid = tid >> 5, lane = tid & 31;
    int wm = wid & 3, wn = wid >> 2;
    int bn0 = blockIdx.x * GBN, bm0 = blockIdx.y * GBM;

    int ldrow = tid >> 2;
    int ldcol = (tid & 3) * 8;

    const __nv_bfloat16* Asel[3] = {Ah, Am, Al};
    const __nv_bfloat16* Wsel[3] = {Wh, Wm, Wl};

    float acc[2][4][4];
    #pragma unroll
    for (int mt = 0; mt < 2; mt++)
        #pragma unroll
        for (int nt = 0; nt < 4; nt++)
            #pragma unroll
            for (int q = 0; q < 4; q++) acc[mt][nt][q] = 0.0f;

    int a_row = (lane & 7) + ((lane >> 3) & 1) * 8;
    int a_ko  = ((lane >> 4) & 1) * 8;
    int b_row = (lane & 7) + ((lane >> 4) & 1) * 8;
    int b_ko  = ((lane >> 3) & 1) * 8;

    auto issue = [&](int st, int k0) {
        #pragma unroll
        for (int s = 0; s < 3; s++) {
            #pragma unroll
            for (int j = 0; j < 2; j++) {
                int row = ldrow + j * 64;
                uint32 dst = smb + (uint32)(st * S6_STG + s * S6_AH + row * ASTR + ldcol) * 2;
                CP16(dst, Asel[s] + (size_t)(bm0 + row) * K + k0 + ldcol);
            }
            uint32 dst = smb + (uint32)(st * S6_STG + 3 * S6_AH + s * S6_BH + ldrow * ASTR + ldcol) * 2;
            CP16(dst, Wsel[s] + (size_t)(bn0 + ldrow) * K + k0 + ldcol);
        }
    };

    int NCH = K / GBK;
    issue(0, 0);
    CP_COMMIT();

    for (int ch = 0; ch < NCH; ch++) {
        if (ch + 1 < NCH) issue((ch + 1) & 1, (ch + 1) * GBK);
        CP_COMMIT();
        CP_WAIT1();
        __syncthreads();

        int st = ch & 1;
        uint32 abase = smb + (uint32)(st * S6_STG) * 2;
        uint32 bbase = smb + (uint32)(st * S6_STG + 3 * S6_AH) * 2;

        #pragma unroll
        for (int ks = 0; ks < 2; ks++) {
            int kc = ks * 16;
            uint32 af[3][2][4];
            #pragma unroll
            for (int s = 0; s < 3; s++)
                #pragma unroll
                for (int mt = 0; mt < 2; mt++)
                    ldsm4(af[s][mt], abase + (uint32)(s * S6_AH + (wm * 32 + mt * 16 + a_row) * ASTR + kc + a_ko) * 2);
            #pragma unroll
            for (int t = 0; t < 3; t++) {
                #pragma unroll
                for (int g = 0; g < 2; g++) {
                    uint32 bf[4];
                    ldsm4(bf, bbase + (uint32)(t * S6_BH + (wn * 32 + g * 16 + b_row) * ASTR + kc + b_ko) * 2);
                    #pragma unroll
                    for (int s = 0; s < 3; s++) {
                        if (s + t <= 2) {
                            mma_bf16(acc[0][2 * g],     af[s][0], bf[0], bf[1]);
                            mma_bf16(acc[1][2 * g],     af[s][1], bf[0], bf[1]);
                            mma_bf16(acc[0][2 * g + 1], af[s][0], bf[2], bf[3]);
                            mma_bf16(acc[1][2 * g + 1], af[s][1], bf[2], bf[3]);
                        }
                    }
                }
            }
        }
        __syncthreads();
    }

    int r4 = lane >> 2, c2 = (lane & 3) * 2;
    #pragma unroll
    for (int nt = 0; nt < 4; nt++) {
        int n0 = bn0 + wn * 32 + nt * 8 + c2;
        float g0 = bnp[n0],     be0 = bnp[N + n0],     mm0 = bnp[2*N + n0],     vv0 = bnp[3*N + n0];
        float g1 = bnp[n0 + 1], be1 = bnp[N + n0 + 1], mm1 = bnp[2*N + n0 + 1], vv1 = bnp[3*N + n0 + 1];
        float sc0 = g0 / sqrtf(vv0 + EPSF), sh0 = be0 - mm0 * sc0;
        float sc1 = g1 / sqrtf(vv1 + EPSF), sh1 = be1 - mm1 * sc1;
        float bs0 = bias[n0], bs1 = bias[n0 + 1];
        #pragma unroll
        for (int mt = 0; mt < 2; mt++) {
            int m0 = bm0 + wm * 32 + mt * 16 + r4;
            float2 o0, o1;
            o0.x = (acc[mt][nt][0] + bs0) * sc0 + sh0;
            o0.y = (acc[mt][nt][1] + bs1) * sc1 + sh1;
            o1.x = (acc[mt][nt][2] + bs0) * sc0 + sh0;
            o1.y = (acc[mt][nt][3] + bs1) * sc1 + sh1;
            *(float2*)&Out[(size_t)m0 * N + n0] = o0;
            *(float2*)&Out[(size_t)(m0 + 8) * N + n0] = o1;
        }
    }
}

// ---------------- fused lif1 -> depthwise -> bn2+lif2 ------------------------
// One block per (b, 64-channel tile). All intermediates stay in smem.
// Numerically identical op sequence to the separate kernels.
#define DW_PAD 15
#define LD_SXP_ROWS (T_DIM + 2 * DW_PAD)     // 158
#define LIFDW_SMEM (LD_SXP_ROWS * 64 * 4 + T_DIM * 64 * 4)   // 40448+32768=73216

__global__ void __launch_bounds__(256) lifdw_kernel(
    const float* __restrict__ Y1, const float* __restrict__ w,
    const float* __restrict__ bvec, const float* __restrict__ bn2p,
    __nv_bfloat16* __restrict__ S2b)
{
    extern __shared__ __align__(16) char smraw[];
    float (*sxp)[64] = (float(*)[64])smraw;                       // [158][64]
    float (*sd)[64]  = (float(*)[64])(smraw + LD_SXP_ROWS * 64 * 4); // [128][64]

    int b  = blockIdx.x;
    int c0 = blockIdx.y * 64;
    int tid = threadIdx.x;

    // zero pads
    for (int i = tid; i < 2 * DW_PAD * 64; i += 256) {
        int r = i >> 6, ci = i & 63;
        if (r < DW_PAD) sxp[r][ci] = 0.0f;
        else            sxp[T_DIM + DW_PAD + (r - DW_PAD)][ci] = 0.0f;
    }
    // load Y1 tile
    for (int i = tid; i < T_DIM * 64; i += 256) {
        int t = i >> 6, ci = i & 63;
        sxp[t + DW_PAD][ci] = Y1[((size_t)t * B_DIM + b) * C_DIM + c0 + ci];
    }
    __syncthreads();

    // lif1 scan in place (spikes overwrite membrane inputs)
    if (tid < 64) {
        float v = 0.0f;
        #pragma unroll 4
        for (int t = 0; t < T_DIM; t++) {
            v = v * 0.5f + sxp[t + DW_PAD][tid];
            float s = (v >= 1.0f) ? 1.0f : 0.0f;
            v = (s > 0.0f) ? 0.0f : v;
            sxp[t + DW_PAD][tid] = s;
        }
    }
    __syncthreads();

    // depthwise conv (identical accumulation order to prior dw_kernel)
    {
        int ci = tid & 63;
        int tg = tid >> 6;
        int c  = c0 + ci;
        int t0 = tg * 32;

        float wr[K_DW];
        #pragma unroll
        for (int k = 0; k < K_DW; k++) wr[k] = w[c * K_DW + k];
        float bb = bvec[c];

        float acc[32];
        #pragma unroll
        for (int i = 0; i < 32; i++) acc[i] = bb;

        #pragma unroll
        for (int dt = -DW_PAD; dt <= 31 + DW_PAD; dt++) {
            float sv = sxp[t0 + dt + DW_PAD][ci];
            #pragma unroll
            for (int i = 0; i < 32; i++) {
                int k = dt - i + DW_PAD;
                if (k >= 0 && k < K_DW) acc[i] += sv * wr[k];
            }
        }
        __syncthreads();
        #pragma unroll
        for (int i = 0; i < 32; i++) sd[t0 + i][ci] = acc[i];
    }
    __syncthreads();

    // bn2 + lif2 scan -> bf16 spikes into sxp region (reused as ushort buffer)
    ushort* sout = (ushort*)smraw;
    if (tid < 64) {
        int c = c0 + tid;
        float g = bn2p[c], be = bn2p[C_DIM + c], mm = bn2p[2 * C_DIM + c], vv = bn2p[3 * C_DIM + c];
        float sc = g / sqrtf(vv + EPSF);
        float sh = be - mm * sc;
        float v = 0.0f;
        #pragma unroll 4
        for (int t = 0; t < T_DIM; t++) {
            float xv = sd[t][tid] * sc + sh;
            v = v * 0.5f + xv;
            float s = (v >= 1.0f) ? 1.0f : 0.0f;
            v = (s > 0.0f) ? 0.0f : v;
            __nv_bfloat16 hb = __float2bfloat16(s);
            sout[t * 64 + tid] = *(ushort*)&hb;
        }
    }
    __syncthreads();

    // coalesced write out
    for (int i = tid; i < T_DIM * 64; i += 256) {
        int t = i >> 6, ci = i & 63;
        ushort u = sout[t * 64 + ci];
        S2b[((size_t)t * B_DIM + b) * C_DIM + c0 + ci] = *(__nv_bfloat16*)&u;
    }
}

// ---------------- LIF scan (plain, bf16 out) ----------------
__global__ void __launch_bounds__(256) lif_gate_kernel(
    const float* __restrict__ X, __nv_bfloat16* __restrict__ S)
{
    int j = blockIdx.x * blockDim.x + threadIdx.x;
    if (j >= B_DIM * C_DIM) return;
    int b = j / C_DIM, c = j % C_DIM;

    const float* xp = X + (size_t)b * 2 * C_DIM + c;
    __nv_bfloat16* sp = S + (size_t)j;
    size_t stx = (size_t)B_DIM * 2 * C_DIM;
    size_t sts = (size_t)B_DIM * C_DIM;

    float vm = 0.0f;
    #pragma unroll 4
    for (int t = 0; t < T_DIM; t++) {
        float xv = xp[(size_t)t * stx];
        vm = vm * 0.5f + xv;
        float s = (vm >= 1.0f) ? 1.0f : 0.0f;
        vm = (s > 0.0f) ? 0.0f : vm;
        sp[(size_t)t * sts] = (__nv_bfloat16)s;
    }
}

// ---------------- fused final double-LIF: s9=lif(Y3); out=lif(Y2out*s9) ------
__global__ void __launch_bounds__(256) lif_final_kernel(
    const float* __restrict__ Y3, const float* __restrict__ Y2out,
    float* __restrict__ Out)
{
    int j = blockIdx.x * blockDim.x + threadIdx.x;
    if (j >= B_DIM * C_DIM) return;
    int b = j / C_DIM, c = j % C_DIM;
    const float* yp = Y3 + (size_t)b * C_DIM + c;
    const float* op = Y2out + (size_t)b * 2 * C_DIM + c;
    float* sp = Out + (size_t)j;
    size_t st3 = (size_t)B_DIM * C_DIM;
    size_t st2 = (size_t)B_DIM * 2 * C_DIM;

    float v9 = 0.0f, v10 = 0.0f;
    #pragma unroll 4
    for (int t = 0; t < T_DIM; t++) {
        float g = yp[(size_t)t * st3];
        v9 = v9 * 0.5f + g;
        float s9 = (v9 >= 1.0f) ? 1.0f : 0.0f;
        v9 = (s9 > 0.0f) ? 0.0f : v9;
        float x = op[(size_t)t * st2] * s9;
        v10 = v10 * 0.5f + x;
        float s10 = (v10 >= 1.0f) ? 1.0f : 0.0f;
        v10 = (s10 > 0.0f) ? 0.0f : v10;
        sp[(size_t)t * st3] = s10;
    }
}

// ---------------- launch ----------------
extern "C" void kernel_launch(void* const* d_in, const int* in_sizes, int n_in,
                              void* d_out, int out_size)
{
    const float* x        = (const float*)d_in[0];
    const float* ln_g     = (const float*)d_in[1];
    const float* ln_b     = (const float*)d_in[2];
    const float* pw1_w    = (const float*)d_in[3];
    const float* pw1_b    = (const float*)d_in[4];
    const float* bn1_p    = (const float*)d_in[5];
    const float* dw_w     = (const float*)d_in[6];
    const float* dw_b     = (const float*)d_in[7];
    const float* bn2_p    = (const float*)d_in[8];
    const float* pw2_w    = (const float*)d_in[9];
    const float* pw2_b    = (const float*)d_in[10];
    const float* bn3_p    = (const float*)d_in[11];
    const float* gsu_w    = (const float*)d_in[12];
    const float* gsu_b    = (const float*)d_in[13];
    const float* gsu_bn_p = (const float*)d_in[14];

    float *Y1, *Y2, *Y3;
    __nv_bfloat16 *S2b, *Sgb, *Hh, *Hm, *Hl;
    __nv_bfloat16 *W1hi, *W1mi, *W1lo, *W2hi, *W2mi, *W2lo, *Wghi, *Wgmi, *Wglo;
    cudaGetSymbolAddress((void**)&Y1,   g_Y1);
    cudaGetSymbolAddress((void**)&Y2,   g_Y2);
    cudaGetSymbolAddress((void**)&Y3,   g_Y3);
    cudaGetSymbolAddress((void**)&S2b,  g_S2b);
    cudaGetSymbolAddress((void**)&Sgb,  g_Sgb);
    cudaGetSymbolAddress((void**)&Hh,   g_Hh);
    cudaGetSymbolAddress((void**)&Hm,   g_Hm);
    cudaGetSymbolAddress((void**)&Hl,   g_Hl);
    cudaGetSymbolAddress((void**)&W1hi, g_W1hi);
    cudaGetSymbolAddress((void**)&W1mi, g_W1mi);
    cudaGetSymbolAddress((void**)&W1lo, g_W1lo);
    cudaGetSymbolAddress((void**)&W2hi, g_W2hi);
    cudaGetSymbolAddress((void**)&W2mi, g_W2mi);
    cudaGetSymbolAddress((void**)&W2lo, g_W2lo);
    cudaGetSymbolAddress((void**)&Wghi, g_Wghi);
    cudaGetSymbolAddress((void**)&Wgmi, g_Wgmi);
    cudaGetSymbolAddress((void**)&Wglo, g_Wglo);

    // idempotent, every invocation
    cudaFuncSetAttribute(gemm_spike_bf16,
        cudaFuncAttributeMaxDynamicSharedMemorySize, SPIKE_SMEM);
    cudaFuncSetAttribute(gemm_split6_bf16,
        cudaFuncAttributeMaxDynamicSharedMemorySize, S6_SMEM);
    cudaFuncSetAttribute(lifdw_kernel,
        cudaFuncAttributeMaxDynamicSharedMemorySize, LIFDW_SMEM);

    const int lif_blocks = (B_DIM * C_DIM + 255) / 256;   // 192

    // 0) weight splits
    split_w_kernel<<<(C_DIM * C_DIM + 255) / 256, 256>>>(pw1_w, W1hi, W1mi, W1lo, C_DIM * C_DIM);
    split_w_kernel<<<(2 * C_DIM * C_DIM + 255) / 256, 256>>>(pw2_w, W2hi, W2mi, W2lo, 2 * C_DIM * C_DIM);
    split_w_kernel<<<(C_DIM * C_DIM + 255) / 256, 256>>>(gsu_w, Wghi, Wgmi, Wglo, C_DIM * C_DIM);

    // 1) LayerNorm -> H splits
    ln_kernel<<<M_DIM, 256>>>(x, ln_g, ln_b, Hh, Hm, Hl);

    // 2) pw1 + bias + bn1 (tensor, 6-term split)
    gemm_split6_bf16<<<dim3(C_DIM / GBN, M_DIM / GBM), 256, S6_SMEM>>>(
        Hh, Hm, Hl, W1hi, W1mi, W1lo, pw1_b, bn1_p, Y1, M_DIM, C_DIM, C_DIM);

    // 3-5) fused: lif1 -> depthwise -> bn2+lif2 -> S2 (bf16)
    lifdw_kernel<<<dim3(B_DIM, C_DIM / 64), 256, LIFDW_SMEM>>>(
        Y1, dw_w, dw_b, bn2_p, S2b);

    // 6) pw2 + bias + bn3 (tensor)
    gemm_spike_bf16<<<dim3(2 * C_DIM / GBN, M_DIM / GBM), 256, SPIKE_SMEM>>>(
        S2b, W2hi, W2mi, W2lo, pw2_b, bn3_p, Y2, M_DIM, 2 * C_DIM, C_DIM);

    // 7) LIF(gate) -> Sg (bf16)
    lif_gate_kernel<<<lif_blocks, 256>>>(Y2 + C_DIM, Sgb);

    // 8) gsu GEMM (tensor)
    gemm_spike_bf16<<<dim3(C_DIM / GBN, M_DIM / GBM), 256, SPIKE_SMEM>>>(
        Sgb, Wghi, Wgmi, Wglo, gsu_b, gsu_bn_p, Y3, M_DIM, C_DIM, C_DIM);

    // 9+10) fused: s9 = lif(Y3); out = lif(Y2out * s9)
    lif_final_kernel<<<lif_blocks, 256>>>(Y3, Y2, (float*)d_out);
}